// round 15
// baseline (speedup 1.0000x reference)
#include <cuda_runtime.h>
#include <cuda_fp16.h>
#include <cstdint>
#include <cstddef>

#define SDIM 256
#define LDIM 192
#define DDIM 256
#define HN   8
#define CN   32
#define NROWS (LDIM*SDIM)
#define SEG  ((size_t)NROWS*DDIM)

#define QSCALE (0.17677669529663687f * 1.4426950408889634f)
#define BIASL2 (-10000.0f * 1.4426950408889634f)

__device__ __half g_XNh[(size_t)NROWS*DDIM];
__device__ __half g_P[(size_t)4*NROWS*DDIM];
__device__ __half g_CTXh[(size_t)NROWS*DDIM];
__device__ __half g_Wh[(size_t)5*DDIM*DDIM];
__device__ float  g_bias[LDIM*SDIM];

// ---------- helpers ----------
__device__ __forceinline__ void mma_f16(float* d, const unsigned* a,
                                        const unsigned* b, const float* c) {
    asm("mma.sync.aligned.m16n8k16.row.col.f32.f16.f16.f32 "
        "{%0,%1,%2,%3}, {%4,%5,%6,%7}, {%8,%9}, {%10,%11,%12,%13};"
        : "=f"(d[0]), "=f"(d[1]), "=f"(d[2]), "=f"(d[3])
        : "r"(a[0]), "r"(a[1]), "r"(a[2]), "r"(a[3]),
          "r"(b[0]), "r"(b[1]),
          "f"(c[0]), "f"(c[1]), "f"(c[2]), "f"(c[3]));
}
__device__ __forceinline__ void ldsm_x4(unsigned& r0, unsigned& r1,
                                        unsigned& r2, unsigned& r3,
                                        uint32_t addr) {
    asm volatile("ldmatrix.sync.aligned.m8n8.x4.shared.b16 {%0,%1,%2,%3}, [%4];"
        : "=r"(r0), "=r"(r1), "=r"(r2), "=r"(r3) : "r"(addr));
}
__device__ __forceinline__ void cp16(uint32_t dst, const void* src) {
    asm volatile("cp.async.cg.shared.global [%0], [%1], 16;"
        :: "r"(dst), "l"(src));
}
__device__ __forceinline__ void cp_commit() {
    asm volatile("cp.async.commit_group;");
}
template <int N>
__device__ __forceinline__ void cp_wait() {
    asm volatile("cp.async.wait_group %0;" :: "n"(N));
}
__device__ __forceinline__ unsigned pack_h2(float a, float b) {
    __half2 h = __floats2half2_rn(a, b);
    return *(unsigned*)&h;
}
__device__ __forceinline__ float fast_exp2(float x) {
    float y;
    asm("ex2.approx.f32 %0, %1;" : "=f"(y) : "f"(x));
    return y;
}

// ============================================================
// Fused preprocessing: ln / wconv / mask in one launch.
// ============================================================
#define LNB (NROWS / 4)
#define WCB (5 * DDIM * DDIM / 256)
#define MKB LDIM

__device__ __forceinline__ int classify_words(const int* w, int nwords) {
    int wordlike = 1;
    for (int i = 0; i < nwords; i++) {
        int v = w[i];
        if (v != 0 && v != 1 && v != 0x3F800000) wordlike = 0;
    }
    return wordlike;
}

__global__ __launch_bounds__(256) void pre_kernel(
    const float* __restrict__ m,
    const float* __restrict__ scale,
    const float* __restrict__ bias,
    const float* __restrict__ wq, const float* __restrict__ wk,
    const float* __restrict__ wv, const float* __restrict__ wg,
    const float* __restrict__ wo,
    const void* __restrict__ seqp, const void* __restrict__ resp) {
    int bid = blockIdx.x;
    if (bid < LNB) {
        int r = bid * 4 + (threadIdx.x >> 6);
        int l = r >> 8;
        int s = r & 255;
        int c0 = (threadIdx.x & 63) << 2;

        float4 v = *(const float4*)(m + ((size_t)(s * LDIM + l)) * DDIM + c0);
        float sum = (v.x + v.y) + (v.z + v.w);
        float sq  = (v.x * v.x + v.y * v.y) + (v.z * v.z + v.w * v.w);
        #pragma unroll
        for (int o = 16; o > 0; o >>= 1) {
            sum += __shfl_xor_sync(0xFFFFFFFFu, sum, o);
            sq  += __shfl_xor_sync(0xFFFFFFFFu, sq, o);
        }
        __shared__ float ssum[8], ssq[8];
        int w = threadIdx.x >> 5;
        if ((threadIdx.x & 31) == 0) { ssum[w] = sum; ssq[w] = sq; }
        __syncthreads();
        int wp = (threadIdx.x >> 6) << 1;
        float S = ssum[wp] + ssum[wp + 1];
        float Q = ssq[wp]  + ssq[wp + 1];
        float mu   = S * (1.0f / DDIM);
        float var  = Q * (1.0f / DDIM) - mu * mu;
        float rstd = rsqrtf(var + 1e-5f);

        float4 sc = *(const float4*)(scale + c0);
        float4 bi = *(const float4*)(bias + c0);
        __half2 h0 = __floats2half2_rn((v.x - mu) * rstd * sc.x + bi.x,
                                       (v.y - mu) * rstd * sc.y + bi.y);
        __half2 h1 = __floats2half2_rn((v.z - mu) * rstd * sc.z + bi.z,
                                       (v.w - mu) * rstd * sc.w + bi.w);
        uint2 o;
        o.x = *(unsigned*)&h0;
        o.y = *(unsigned*)&h1;
        *(uint2*)(g_XNh + (size_t)r * DDIM + c0) = o;
    } else if (bid < LNB + WCB) {
        int j = (bid - LNB) * 256 + threadIdx.x;
        int mat = j >> 16;
        int i = j & 65535;
        const float* src = (mat == 0) ? wq : (mat == 1) ? wk :
                           (mat == 2) ? wv : (mat == 3) ? wg : wo;
        g_Wh[(size_t)mat * DDIM * DDIM + i] = __float2half(src[i]);
    } else {
        __shared__ int s_seqw, s_resw;
        if (threadIdx.x == 0) {
            s_seqw = classify_words((const int*)seqp, 64);
            s_resw = classify_words((const int*)resp, 48);
        }
        __syncthreads();
        const int seqw = s_seqw, resw = s_resw;
        int idx = (bid - LNB - WCB) * 256 + threadIdx.x;
        int l = idx >> 8;
        int t = idx & 255;
        int rp = resw ? (((const int*)resp)[l] != 0)
                      : (((const unsigned char*)resp)[l] != 0);
        int sp = seqw ? (((const int*)seqp)[t] != 0)
                      : (((const unsigned char*)seqp)[t] != 0);
        g_bias[idx] = (rp | sp) ? BIASL2 : 0.0f;
    }
}

// ============================================================
// Projection GEMM (R9-exact)
// ============================================================
#define GSTG (128 * 40)
#define GEMM_SMEM_BYTES (3 * 2 * GSTG * 2)

__global__ __launch_bounds__(256, 2) void proj_mma_kernel(
    const float* __restrict__ bgv) {
    extern __shared__ __half sbuf[];

    int tid = threadIdx.x, warp = tid >> 5, lane = tid & 31;
    int lr = lane >> 2, lc4 = lane & 3;
    int wm = (warp >> 1) << 5;
    int wn = (warp & 1) << 6;

    int r0  = blockIdx.x << 7;
    int mat = blockIdx.y >> 1;
    int n0  = (blockIdx.y & 1) << 7;
    const __half* W = g_Wh + (size_t)mat * DDIM * DDIM;

    int row0 = tid >> 2,           col0 = (tid & 3) << 3;
    int row1 = (tid + 256) >> 2,   col1 = col0;
    const __half* Aip0 = g_XNh + (size_t)(r0 + row0) * 256 + col0;
    const __half* Aip1 = g_XNh + (size_t)(r0 + row1) * 256 + col1;
    const __half* Bip0 = W     + (size_t)(n0 + row0) * 256 + col0;
    const __half* Bip1 = W     + (size_t)(n0 + row1) * 256 + col1;

    uint32_t sb = (uint32_t)__cvta_generic_to_shared(sbuf);
    uint32_t dA0 = sb + ((unsigned)(row0 * 40 + col0) << 1);
    uint32_t dA1 = sb + ((unsigned)(row1 * 40 + col1) << 1);
    uint32_t dB0 = dA0 + GSTG * 2;
    uint32_t dB1 = dA1 + GSTG * 2;
    const uint32_t stg = 2 * GSTG * 2;

    int li15 = lane & 15, li7 = lane & 7;
    int a_coff = (lane >> 4) << 3;
    int b_roff = ((lane >> 4) << 3) + li7;
    int b_coff = ((lane >> 3) & 1) << 3;

    float acc[16][4] = {};

    #pragma unroll
    for (int s = 0; s < 2; s++) {
        int k0 = s * 32;
        cp16(dA0 + s * stg, Aip0 + k0);
        cp16(dA1 + s * stg, Aip1 + k0);
        cp16(dB0 + s * stg, Bip0 + k0);
        cp16(dB1 + s * stg, Bip1 + k0);
        cp_commit();
    }

    for (int t = 0; t < 8; t++) {
        if (t < 7) cp_wait<1>(); else cp_wait<0>();
        __syncthreads();
        if (t + 2 < 8) {
            int s = (t + 2) % 3;
            int k0 = (t + 2) * 32;
            cp16(dA0 + s * stg, Aip0 + k0);
            cp16(dA1 + s * stg, Aip1 + k0);
            cp16(dB0 + s * stg, Bip0 + k0);
            cp16(dB1 + s * stg, Bip1 + k0);
            cp_commit();
        }
        uint32_t As_s = sb + (t % 3) * stg;
        uint32_t Bs_s = As_s + GSTG * 2;
        #pragma unroll
        for (int ks = 0; ks < 2; ks++) {
            unsigned af[2][4], bf[8][2];
            #pragma unroll
            for (int mt = 0; mt < 2; mt++) {
                uint32_t a = As_s +
                    ((unsigned)((wm + mt * 16 + li15) * 40 + ks * 16 + a_coff) << 1);
                ldsm_x4(af[mt][0], af[mt][1], af[mt][2], af[mt][3], a);
            }
            #pragma unroll
            for (int p = 0; p < 4; p++) {
                uint32_t b = Bs_s +
                    ((unsigned)((wn + p * 16 + b_roff) * 40 + ks * 16 + b_coff) << 1);
                ldsm_x4(bf[2 * p][0], bf[2 * p][1],
                        bf[2 * p + 1][0], bf[2 * p + 1][1], b);
            }
            #pragma unroll
            for (int mt = 0; mt < 2; mt++)
                #pragma unroll
                for (int nt = 0; nt < 8; nt++)
                    mma_f16(acc[mt * 8 + nt], af[mt], bf[nt], acc[mt * 8 + nt]);
        }
    }

    #pragma unroll
    for (int mt = 0; mt < 2; mt++)
        #pragma unroll
        for (int nt = 0; nt < 8; nt++) {
            int n = n0 + wn + nt * 8 + (lc4 << 1);
            int h = n >> 5, c = n & 31;
            #pragma unroll
            for (int hf = 0; hf < 2; hf++) {
                int r = r0 + wm + mt * 16 + lr + hf * 8;
                int l = r >> 8, s = r & 255;
                float v0 = acc[mt * 8 + nt][hf * 2 + 0];
                float v1 = acc[mt * 8 + nt][hf * 2 + 1];
                if (mat == 0) {
                    v0 *= QSCALE;
                    v1 *= QSCALE;
                } else if (mat == 3) {
                    v0 = 1.0f / (1.0f + __expf(-(v0 + bgv[n])));
                    v1 = 1.0f / (1.0f + __expf(-(v1 + bgv[n + 1])));
                }
                __half* dst = g_P + (size_t)mat * SEG
                            + ((size_t)((l * HN + h) * SDIM + s)) * CN + c;
                *(__half2*)dst = __floats2half2_rn(v0, v1);
            }
        }
}

// ============================================================
// Attention v5: 2 CTAs per (l,h), warp = 16 queries, 8 warps =
// 128 queries/CTA, 3 CTA/SM target. fp16 mma + ldsm, exp2
// softmax, deferred sums. Smem identical to R9 layout.
// ============================================================
#define KP 40
#define VP 264
#define ATTN_SMEM_BYTES (256*KP*2 + 32*VP*2 + 256*4)

__global__ __launch_bounds__(256, 3) void attn_mma_kernel() {
    extern __shared__ char smem_raw[];
    __half* Ks = (__half*)smem_raw;
    __half* Vt = (__half*)(smem_raw + 256 * KP * 2);
    float*  Bb = (float*)(smem_raw + 256 * KP * 2 + 32 * VP * 2);

    int bid = blockIdx.x;
    int lh = bid >> 1;
    int qhalf = bid & 1;
    int l = lh >> 3, h = lh & 7;
    size_t base = (size_t)lh * SDIM * CN;
    const __half* Qg = g_P + base;
    const __half* Kg = g_P + SEG + base;
    const __half* Vg = g_P + 2 * SEG + base;
    const __half* Gg = g_P + 3 * SEG + base;

    int tid = threadIdx.x, warp = tid >> 5, lane = tid & 31;
    int lr = lane >> 2, lc4 = lane & 3;
    int li7 = lane & 7;
    int b_roff = ((lane >> 4) << 3) + li7;
    int b_coff = ((lane >> 3) & 1) << 3;

    uint32_t Ks_s = (uint32_t)__cvta_generic_to_shared(Ks);
    uint32_t Vt_s = (uint32_t)__cvta_generic_to_shared(Vt);

    #pragma unroll
    for (int i = 0; i < 8; i++) {
        int idx = tid + (i << 8);
        int t = idx >> 3, c4 = (idx & 7) << 2;
        *(uint2*)(Ks + t * KP + c4) = *(const uint2*)(Kg + t * 32 + c4);
        __half2 v01 = *(const __half2*)(Vg + t * 32 + c4);
        __half2 v23 = *(const __half2*)(Vg + t * 32 + c4 + 2);
        Vt[(c4 + 0) * VP + t] = __low2half(v01);
        Vt[(c4 + 1) * VP + t] = __high2half(v01);
        Vt[(c4 + 2) * VP + t] = __low2half(v23);
        Vt[(c4 + 3) * VP + t] = __high2half(v23);
    }
    Bb[tid] = g_bias[l * SDIM + tid];
    __syncthreads();

    int qb = qhalf * 128 + warp * 16;
    unsigned qf[2][4];
    #pragma unroll
    for (int kt = 0; kt < 2; kt++) {
        int c = kt * 16 + (lc4 << 1);
        qf[kt][0] = *(const unsigned*)(Qg + (qb + lr) * 32 + c);
        qf[kt][1] = *(const unsigned*)(Qg + (qb + lr + 8) * 32 + c);
        qf[kt][2] = *(const unsigned*)(Qg + (qb + lr) * 32 + c + 8);
        qf[kt][3] = *(const unsigned*)(Qg + (qb + lr + 8) * 32 + c + 8);
    }

    float mrow[2] = {-3.0e38f, -3.0e38f};
    float srow[2] = {0.f, 0.f};
    float ctx[4][4] = {};

    for (int t0 = 0; t0 < 256; t0 += 32) {
        float lg[4][4] = {};
        #pragma unroll
        for (int kt = 0; kt < 2; kt++) {
            unsigned bf[4][2];
            #pragma unroll
            for (int p = 0; p < 2; p++) {
                uint32_t a = Ks_s +
                    ((unsigned)((t0 + p * 16 + b_roff) * KP + kt * 16 + b_coff) << 1);
                ldsm_x4(bf[2 * p][0], bf[2 * p][1],
                        bf[2 * p + 1][0], bf[2 * p + 1][1], a);
            }
            #pragma unroll
            for (int nt = 0; nt < 4; nt++)
                mma_f16(lg[nt], qf[kt], bf[nt], lg[nt]);
        }
        float cmax[2] = {-3.0e38f, -3.0e38f};
        #pragma unroll
        for (int nt = 0; nt < 4; nt++) {
            float2 b2 = *(const float2*)&Bb[t0 + nt * 8 + (lc4 << 1)];
            lg[nt][0] += b2.x; lg[nt][1] += b2.y;
            lg[nt][2] += b2.x; lg[nt][3] += b2.y;
            cmax[0] = fmaxf(cmax[0], fmaxf(lg[nt][0], lg[nt][1]));
            cmax[1] = fmaxf(cmax[1], fmaxf(lg[nt][2], lg[nt][3]));
        }
        float corr[2];
        #pragma unroll
        for (int hf = 0; hf < 2; hf++) {
            float v = cmax[hf];
            v = fmaxf(v, __shfl_xor_sync(0xFFFFFFFFu, v, 1));
            v = fmaxf(v, __shfl_xor_sync(0xFFFFFFFFu, v, 2));
            float nm = fmaxf(mrow[hf], v);
            corr[hf] = fast_exp2(mrow[hf] - nm);
            mrow[hf] = nm;
        }
        float c0 = 0.f, c1 = 0.f;
        #pragma unroll
        for (int nt = 0; nt < 4; nt++) {
            float p0 = fast_exp2(lg[nt][0] - mrow[0]);
            float p1 = fast_exp2(lg[nt][1] - mrow[0]);
            float p2 = fast_exp2(lg[nt][2] - mrow[1]);
            float p3 = fast_exp2(lg[nt][3] - mrow[1]);
            c0 += p0 + p1;
            c1 += p2 + p3;
            lg[nt][0] = p0; lg[nt][1] = p1;
            lg[nt][2] = p2; lg[nt][3] = p3;
        }
        srow[0] = srow[0] * corr[0] + c0;
        srow[1] = srow[1] * corr[1] + c1;
        #pragma unroll
        for (int ct = 0; ct < 4; ct++) {
            ctx[ct][0] *= corr[0];
            ctx[ct][1] *= corr[0];
            ctx[ct][2] *= corr[1];
            ctx[ct][3] *= corr[1];
        }
        #pragma unroll
        for (int ks2 = 0; ks2 < 2; ks2++) {
            unsigned pa[4];
            pa[0] = pack_h2(lg[2 * ks2][0],     lg[2 * ks2][1]);
            pa[1] = pack_h2(lg[2 * ks2][2],     lg[2 * ks2][3]);
            pa[2] = pack_h2(lg[2 * ks2 + 1][0], lg[2 * ks2 + 1][1]);
            pa[3] = pack_h2(lg[2 * ks2 + 1][2], lg[2 * ks2 + 1][3]);
            unsigned vb[4][2];
            #pragma unroll
            for (int p = 0; p < 2; p++) {
                uint32_t a = Vt_s +
                    ((unsigned)((p * 16 + b_roff) * VP + t0 + ks2 * 16 + b_coff) << 1);
                ldsm_x4(vb[2 * p][0], vb[2 * p][1],
                        vb[2 * p + 1][0], vb[2 * p + 1][1], a);
            }
            #pragma unroll
            for (int ct = 0; ct < 4; ct++)
                mma_f16(ctx[ct], pa, vb[ct], ctx[ct]);
        }
    }

    float inv[2];
    #pragma unroll
    for (int hf = 0; hf < 2; hf++) {
        float v = srow[hf];
        v += __shfl_xor_sync(0xFFFFFFFFu, v, 1);
        v += __shfl_xor_sync(0xFFFFFFFFu, v, 2);
        inv[hf] = 1.0f / v;
    }
    #pragma unroll
    for (int ct = 0; ct < 4; ct++) {
        int c = ct * 8 + (lc4 << 1);
        #pragma unroll
        for (int hf = 0; hf < 2; hf++) {
            int s = qb + lr + hf * 8;
            float2 g2 = __half22float2(*(const __half2*)(Gg + s * 32 + c));
            float ox = ctx[ct][hf * 2 + 0] * inv[hf] * g2.x;
            float oy = ctx[ct][hf * 2 + 1] * inv[hf] * g2.y;
            *(__half2*)(g_CTXh + ((size_t)(l * SDIM + s)) * DDIM + h * CN + c) =
                __floats2half2_rn(ox, oy);
        }
    }
}

// ============================================================
// Output GEMM (R9-exact)
// ============================================================
__global__ __launch_bounds__(256, 2) void out_mma_kernel(
    const float* __restrict__ bo, float* __restrict__ out) {
    extern __shared__ __half sbuf[];

    int tid = threadIdx.x, warp = tid >> 5, lane = tid & 31;
    int lr = lane >> 2, lc4 = lane & 3;
    int wm = (warp >> 1) << 5;
    int wn = (warp & 1) << 6;

    int r0 = blockIdx.x << 7;
    int n0 = blockIdx.y << 7;
    const __half* W = g_Wh + (size_t)4 * DDIM * DDIM;

    int row0 = tid >> 2,         col0 = (tid & 3) << 3;
    int row1 = (tid + 256) >> 2, col1 = col0;
    const __half* Aip0 = g_CTXh + (size_t)(r0 + row0) * 256 + col0;
    const __half* Aip1 = g_CTXh + (size_t)(r0 + row1) * 256 + col1;
    const __half* Bip0 = W      + (size_t)(n0 + row0) * 256 + col0;
    const __half* Bip1 = W      + (size_t)(n0 + row1) * 256 + col1;

    uint32_t sb = (uint32_t)__cvta_generic_to_shared(sbuf);
    uint32_t dA0 = sb + ((unsigned)(row0 * 40 + col0) << 1);
    uint32_t dA1 = sb + ((unsigned)(row1 * 40 + col1) << 1);
    uint32_t dB0 = dA0 + GSTG * 2;
    uint32_t dB1 = dA1 + GSTG * 2;
    const uint32_t stg = 2 * GSTG * 2;

    int li15 = lane & 15, li7 = lane & 7;
    int a_coff = (lane >> 4) << 3;
    int b_roff = ((lane >> 4) << 3) + li7;
    int b_coff = ((lane >> 3) & 1) << 3;

    float acc[16][4] = {};

    #pragma unroll
    for (int s = 0; s < 2; s++) {
        int k0 = s * 32;
        cp16(dA0 + s * stg, Aip0 + k0);
        cp16(dA1 + s * stg, Aip1 + k0);
        cp16(dB0 + s * stg, Bip0 + k0);
        cp16(dB1 + s * stg, Bip1 + k0);
        cp_commit();
    }

    for (int t = 0; t < 8; t++) {
        if (t < 7) cp_wait<1>(); else cp_wait<0>();
        __syncthreads();
        if (t + 2 < 8) {
            int s = (t + 2) % 3;
            int k0 = (t + 2) * 32;
            cp16(dA0 + s * stg, Aip0 + k0);
            cp16(dA1 + s * stg, Aip1 + k0);
            cp16(dB0 + s * stg, Bip0 + k0);
            cp16(dB1 + s * stg, Bip1 + k0);
            cp_commit();
        }
        uint32_t As_s = sb + (t % 3) * stg;
        uint32_t Bs_s = As_s + GSTG * 2;
        #pragma unroll
        for (int ks = 0; ks < 2; ks++) {
            unsigned af[2][4], bf[8][2];
            #pragma unroll
            for (int mt = 0; mt < 2; mt++) {
                uint32_t a = As_s +
                    ((unsigned)((wm + mt * 16 + li15) * 40 + ks * 16 + a_coff) << 1);
                ldsm_x4(af[mt][0], af[mt][1], af[mt][2], af[mt][3], a);
            }
            #pragma unroll
            for (int p = 0; p < 4; p++) {
                uint32_t b = Bs_s +
                    ((unsigned)((wn + p * 16 + b_roff) * 40 + ks * 16 + b_coff) << 1);
                ldsm_x4(bf[2 * p][0], bf[2 * p][1],
                        bf[2 * p + 1][0], bf[2 * p + 1][1], b);
            }
            #pragma unroll
            for (int mt = 0; mt < 2; mt++)
                #pragma unroll
                for (int nt = 0; nt < 8; nt++)
                    mma_f16(acc[mt * 8 + nt], af[mt], bf[nt], acc[mt * 8 + nt]);
        }
    }

    #pragma unroll
    for (int mt = 0; mt < 2; mt++)
        #pragma unroll
        for (int nt = 0; nt < 8; nt++) {
            int n = n0 + wn + nt * 8 + (lc4 << 1);
            #pragma unroll
            for (int hf = 0; hf < 2; hf++) {
                int r = r0 + wm + mt * 16 + lr + hf * 8;
                int l = r >> 8, s = r & 255;
                float2 o;
                o.x = acc[mt * 8 + nt][hf * 2 + 0] + bo[n];
                o.y = acc[mt * 8 + nt][hf * 2 + 1] + bo[n + 1];
                *(float2*)(out + (size_t)(s * LDIM + l) * DDIM + n) = o;
            }
        }
}

// ============================================================
extern "C" void kernel_launch(void* const* d_in, const int* in_sizes, int n_in,
                              void* d_out, int out_size) {
    const float* m        = (const float*)d_in[0];
    const void*  seqp     = d_in[1];
    const void*  resp     = d_in[2];
    const float* ln_scale = (const float*)d_in[3];
    const float* ln_bias  = (const float*)d_in[4];
    const float* wq       = (const float*)d_in[5];
    const float* wk       = (const float*)d_in[6];
    const float* wv       = (const float*)d_in[7];
    const float* wg       = (const float*)d_in[8];
    const float* bg       = (const float*)d_in[9];
    const float* wo       = (const float*)d_in[10];
    const float* bo       = (const float*)d_in[11];
    float* out = (float*)d_out;

    cudaFuncSetAttribute(proj_mma_kernel,
                         cudaFuncAttributeMaxDynamicSharedMemorySize, GEMM_SMEM_BYTES);
    cudaFuncSetAttribute(out_mma_kernel,
                         cudaFuncAttributeMaxDynamicSharedMemorySize, GEMM_SMEM_BYTES);
    cudaFuncSetAttribute(attn_mma_kernel,
                         cudaFuncAttributeMaxDynamicSharedMemorySize, ATTN_SMEM_BYTES);

    pre_kernel<<<LNB + WCB + MKB, 256>>>(m, ln_scale, ln_bias,
                                         wq, wk, wv, wg, wo, seqp, resp);
    proj_mma_kernel<<<dim3(NROWS / 128, 8), 256, GEMM_SMEM_BYTES>>>(bg);
    attn_mma_kernel<<<LDIM * HN * 2, 256, ATTN_SMEM_BYTES>>>();
    out_mma_kernel<<<dim3(NROWS / 128, 2), 256, GEMM_SMEM_BYTES>>>(bo, out);
}

// round 16
// speedup vs baseline: 1.0124x; 1.0124x over previous
#include <cuda_runtime.h>
#include <cuda_fp16.h>
#include <cstdint>
#include <cstddef>

#define SDIM 256
#define LDIM 192
#define DDIM 256
#define HN   8
#define CN   32
#define NROWS (LDIM*SDIM)
#define SEG  ((size_t)NROWS*DDIM)

#define QSCALE (0.17677669529663687f * 1.4426950408889634f)
#define BIASL2 (-10000.0f * 1.4426950408889634f)

__device__ __half g_XNh[(size_t)NROWS*DDIM];
__device__ __half g_P[(size_t)4*NROWS*DDIM];
__device__ __half g_CTXh[(size_t)NROWS*DDIM];
__device__ __half g_Wh[(size_t)5*DDIM*DDIM];
__device__ float  g_bias[LDIM*SDIM];

// ---------- helpers ----------
__device__ __forceinline__ void mma_f16(float* d, const unsigned* a,
                                        const unsigned* b, const float* c) {
    asm("mma.sync.aligned.m16n8k16.row.col.f32.f16.f16.f32 "
        "{%0,%1,%2,%3}, {%4,%5,%6,%7}, {%8,%9}, {%10,%11,%12,%13};"
        : "=f"(d[0]), "=f"(d[1]), "=f"(d[2]), "=f"(d[3])
        : "r"(a[0]), "r"(a[1]), "r"(a[2]), "r"(a[3]),
          "r"(b[0]), "r"(b[1]),
          "f"(c[0]), "f"(c[1]), "f"(c[2]), "f"(c[3]));
}
__device__ __forceinline__ void ldsm_x4(unsigned& r0, unsigned& r1,
                                        unsigned& r2, unsigned& r3,
                                        uint32_t addr) {
    asm volatile("ldmatrix.sync.aligned.m8n8.x4.shared.b16 {%0,%1,%2,%3}, [%4];"
        : "=r"(r0), "=r"(r1), "=r"(r2), "=r"(r3) : "r"(addr));
}
__device__ __forceinline__ void cp16(uint32_t dst, const void* src) {
    asm volatile("cp.async.cg.shared.global [%0], [%1], 16;"
        :: "r"(dst), "l"(src));
}
__device__ __forceinline__ void cp_commit() {
    asm volatile("cp.async.commit_group;");
}
template <int N>
__device__ __forceinline__ void cp_wait() {
    asm volatile("cp.async.wait_group %0;" :: "n"(N));
}
__device__ __forceinline__ unsigned pack_h2(float a, float b) {
    __half2 h = __floats2half2_rn(a, b);
    return *(unsigned*)&h;
}
__device__ __forceinline__ float fast_exp2(float x) {
    float y;
    asm("ex2.approx.f32 %0, %1;" : "=f"(y) : "f"(x));
    return y;
}

// ============================================================
// Fused preprocessing: ln / wconv / mask in one launch.
// ============================================================
#define LNB (NROWS / 4)
#define WCB (5 * DDIM * DDIM / 256)
#define MKB LDIM

__device__ __forceinline__ int classify_words(const int* w, int nwords) {
    int wordlike = 1;
    for (int i = 0; i < nwords; i++) {
        int v = w[i];
        if (v != 0 && v != 1 && v != 0x3F800000) wordlike = 0;
    }
    return wordlike;
}

__global__ __launch_bounds__(256) void pre_kernel(
    const float* __restrict__ m,
    const float* __restrict__ scale,
    const float* __restrict__ bias,
    const float* __restrict__ wq, const float* __restrict__ wk,
    const float* __restrict__ wv, const float* __restrict__ wg,
    const float* __restrict__ wo,
    const void* __restrict__ seqp, const void* __restrict__ resp) {
    int bid = blockIdx.x;
    if (bid < LNB) {
        int r = bid * 4 + (threadIdx.x >> 6);
        int l = r >> 8;
        int s = r & 255;
        int c0 = (threadIdx.x & 63) << 2;

        float4 v = *(const float4*)(m + ((size_t)(s * LDIM + l)) * DDIM + c0);
        float sum = (v.x + v.y) + (v.z + v.w);
        float sq  = (v.x * v.x + v.y * v.y) + (v.z * v.z + v.w * v.w);
        #pragma unroll
        for (int o = 16; o > 0; o >>= 1) {
            sum += __shfl_xor_sync(0xFFFFFFFFu, sum, o);
            sq  += __shfl_xor_sync(0xFFFFFFFFu, sq, o);
        }
        __shared__ float ssum[8], ssq[8];
        int w = threadIdx.x >> 5;
        if ((threadIdx.x & 31) == 0) { ssum[w] = sum; ssq[w] = sq; }
        __syncthreads();
        int wp = (threadIdx.x >> 6) << 1;
        float S = ssum[wp] + ssum[wp + 1];
        float Q = ssq[wp]  + ssq[wp + 1];
        float mu   = S * (1.0f / DDIM);
        float var  = Q * (1.0f / DDIM) - mu * mu;
        float rstd = rsqrtf(var + 1e-5f);

        float4 sc = *(const float4*)(scale + c0);
        float4 bi = *(const float4*)(bias + c0);
        __half2 h0 = __floats2half2_rn((v.x - mu) * rstd * sc.x + bi.x,
                                       (v.y - mu) * rstd * sc.y + bi.y);
        __half2 h1 = __floats2half2_rn((v.z - mu) * rstd * sc.z + bi.z,
                                       (v.w - mu) * rstd * sc.w + bi.w);
        uint2 o;
        o.x = *(unsigned*)&h0;
        o.y = *(unsigned*)&h1;
        *(uint2*)(g_XNh + (size_t)r * DDIM + c0) = o;
    } else if (bid < LNB + WCB) {
        int j = (bid - LNB) * 256 + threadIdx.x;
        int mat = j >> 16;
        int i = j & 65535;
        const float* src = (mat == 0) ? wq : (mat == 1) ? wk :
                           (mat == 2) ? wv : (mat == 3) ? wg : wo;
        g_Wh[(size_t)mat * DDIM * DDIM + i] = __float2half(src[i]);
    } else {
        __shared__ int s_seqw, s_resw;
        if (threadIdx.x == 0) {
            s_seqw = classify_words((const int*)seqp, 64);
            s_resw = classify_words((const int*)resp, 48);
        }
        __syncthreads();
        const int seqw = s_seqw, resw = s_resw;
        int idx = (bid - LNB - WCB) * 256 + threadIdx.x;
        int l = idx >> 8;
        int t = idx & 255;
        int rp = resw ? (((const int*)resp)[l] != 0)
                      : (((const unsigned char*)resp)[l] != 0);
        int sp = seqw ? (((const int*)seqp)[t] != 0)
                      : (((const unsigned char*)seqp)[t] != 0);
        g_bias[idx] = (rp | sp) ? BIASL2 : 0.0f;
    }
}

// ============================================================
// Projection GEMM (R9-exact)
// ============================================================
#define GSTG (128 * 40)
#define GEMM_SMEM_BYTES (3 * 2 * GSTG * 2)

__global__ __launch_bounds__(256, 2) void proj_mma_kernel(
    const float* __restrict__ bgv) {
    extern __shared__ __half sbuf[];

    int tid = threadIdx.x, warp = tid >> 5, lane = tid & 31;
    int lr = lane >> 2, lc4 = lane & 3;
    int wm = (warp >> 1) << 5;
    int wn = (warp & 1) << 6;

    int r0  = blockIdx.x << 7;
    int mat = blockIdx.y >> 1;
    int n0  = (blockIdx.y & 1) << 7;
    const __half* W = g_Wh + (size_t)mat * DDIM * DDIM;

    int row0 = tid >> 2,           col0 = (tid & 3) << 3;
    int row1 = (tid + 256) >> 2,   col1 = col0;
    const __half* Aip0 = g_XNh + (size_t)(r0 + row0) * 256 + col0;
    const __half* Aip1 = g_XNh + (size_t)(r0 + row1) * 256 + col1;
    const __half* Bip0 = W     + (size_t)(n0 + row0) * 256 + col0;
    const __half* Bip1 = W     + (size_t)(n0 + row1) * 256 + col1;

    uint32_t sb = (uint32_t)__cvta_generic_to_shared(sbuf);
    uint32_t dA0 = sb + ((unsigned)(row0 * 40 + col0) << 1);
    uint32_t dA1 = sb + ((unsigned)(row1 * 40 + col1) << 1);
    uint32_t dB0 = dA0 + GSTG * 2;
    uint32_t dB1 = dA1 + GSTG * 2;
    const uint32_t stg = 2 * GSTG * 2;

    int li15 = lane & 15, li7 = lane & 7;
    int a_coff = (lane >> 4) << 3;
    int b_roff = ((lane >> 4) << 3) + li7;
    int b_coff = ((lane >> 3) & 1) << 3;

    float acc[16][4] = {};

    #pragma unroll
    for (int s = 0; s < 2; s++) {
        int k0 = s * 32;
        cp16(dA0 + s * stg, Aip0 + k0);
        cp16(dA1 + s * stg, Aip1 + k0);
        cp16(dB0 + s * stg, Bip0 + k0);
        cp16(dB1 + s * stg, Bip1 + k0);
        cp_commit();
    }

    for (int t = 0; t < 8; t++) {
        if (t < 7) cp_wait<1>(); else cp_wait<0>();
        __syncthreads();
        if (t + 2 < 8) {
            int s = (t + 2) % 3;
            int k0 = (t + 2) * 32;
            cp16(dA0 + s * stg, Aip0 + k0);
            cp16(dA1 + s * stg, Aip1 + k0);
            cp16(dB0 + s * stg, Bip0 + k0);
            cp16(dB1 + s * stg, Bip1 + k0);
            cp_commit();
        }
        uint32_t As_s = sb + (t % 3) * stg;
        uint32_t Bs_s = As_s + GSTG * 2;
        #pragma unroll
        for (int ks = 0; ks < 2; ks++) {
            unsigned af[2][4], bf[8][2];
            #pragma unroll
            for (int mt = 0; mt < 2; mt++) {
                uint32_t a = As_s +
                    ((unsigned)((wm + mt * 16 + li15) * 40 + ks * 16 + a_coff) << 1);
                ldsm_x4(af[mt][0], af[mt][1], af[mt][2], af[mt][3], a);
            }
            #pragma unroll
            for (int p = 0; p < 4; p++) {
                uint32_t b = Bs_s +
                    ((unsigned)((wn + p * 16 + b_roff) * 40 + ks * 16 + b_coff) << 1);
                ldsm_x4(bf[2 * p][0], bf[2 * p][1],
                        bf[2 * p + 1][0], bf[2 * p + 1][1], b);
            }
            #pragma unroll
            for (int mt = 0; mt < 2; mt++)
                #pragma unroll
                for (int nt = 0; nt < 8; nt++)
                    mma_f16(acc[mt * 8 + nt], af[mt], bf[nt], acc[mt * 8 + nt]);
        }
    }

    #pragma unroll
    for (int mt = 0; mt < 2; mt++)
        #pragma unroll
        for (int nt = 0; nt < 8; nt++) {
            int n = n0 + wn + nt * 8 + (lc4 << 1);
            int h = n >> 5, c = n & 31;
            #pragma unroll
            for (int hf = 0; hf < 2; hf++) {
                int r = r0 + wm + mt * 16 + lr + hf * 8;
                int l = r >> 8, s = r & 255;
                float v0 = acc[mt * 8 + nt][hf * 2 + 0];
                float v1 = acc[mt * 8 + nt][hf * 2 + 1];
                if (mat == 0) {
                    v0 *= QSCALE;
                    v1 *= QSCALE;
                } else if (mat == 3) {
                    v0 = 1.0f / (1.0f + __expf(-(v0 + bgv[n])));
                    v1 = 1.0f / (1.0f + __expf(-(v1 + bgv[n + 1])));
                }
                __half* dst = g_P + (size_t)mat * SEG
                            + ((size_t)((l * HN + h) * SDIM + s)) * CN + c;
                *(__half2*)dst = __floats2half2_rn(v0, v1);
            }
        }
}

// ============================================================
// Attention (R12 shape: 1 CTA per (l,h), m=32 warps, 2 CTA/SM)
// with uint4-vectorized K/V staging.
// ============================================================
#define KP 40
#define VP 264
#define ATTN_SMEM_BYTES (256*KP*2 + 32*VP*2 + 256*4)

__global__ __launch_bounds__(256, 2) void attn_mma_kernel() {
    extern __shared__ char smem_raw[];
    __half* Ks = (__half*)smem_raw;
    __half* Vt = (__half*)(smem_raw + 256 * KP * 2);
    float*  Bb = (float*)(smem_raw + 256 * KP * 2 + 32 * VP * 2);

    int lh = blockIdx.x;
    int l = lh >> 3, h = lh & 7;
    size_t base = (size_t)lh * SDIM * CN;
    const __half* Qg = g_P + base;
    const __half* Kg = g_P + SEG + base;
    const __half* Vg = g_P + 2 * SEG + base;
    const __half* Gg = g_P + 3 * SEG + base;

    int tid = threadIdx.x, warp = tid >> 5, lane = tid & 31;
    int lr = lane >> 2, lc4 = lane & 3;
    int li7 = lane & 7;
    int b_roff = ((lane >> 4) << 3) + li7;
    int b_coff = ((lane >> 3) & 1) << 3;

    uint32_t Ks_s = (uint32_t)__cvta_generic_to_shared(Ks);
    uint32_t Vt_s = (uint32_t)__cvta_generic_to_shared(Vt);

    // staging: thread handles 4 chunks of 8 halfs (uint4) for K and V
    #pragma unroll
    for (int i = 0; i < 4; i++) {
        int idx = tid + (i << 8);          // 1024 chunks of 8 halfs
        int t = idx >> 2, c8 = (idx & 3) << 3;
        uint4 kv = *(const uint4*)(Kg + t * 32 + c8);
        *(uint4*)(Ks + t * KP + c8) = kv;
        uint4 vv = *(const uint4*)(Vg + t * 32 + c8);
        const __half2* vh = (const __half2*)&vv;
        #pragma unroll
        for (int j = 0; j < 4; j++) {
            Vt[(c8 + 2 * j + 0) * VP + t] = __low2half(vh[j]);
            Vt[(c8 + 2 * j + 1) * VP + t] = __high2half(vh[j]);
        }
    }
    Bb[tid] = g_bias[l * SDIM + tid];
    __syncthreads();

    int qb = warp << 5;
    unsigned qf[2][2][4];
    #pragma unroll
    for (int kt = 0; kt < 2; kt++)
        #pragma unroll
        for (int mt = 0; mt < 2; mt++) {
            int r = qb + mt * 16 + lr;
            int c = kt * 16 + (lc4 << 1);
            qf[kt][mt][0] = *(const unsigned*)(Qg + r * 32 + c);
            qf[kt][mt][1] = *(const unsigned*)(Qg + (r + 8) * 32 + c);
            qf[kt][mt][2] = *(const unsigned*)(Qg + r * 32 + c + 8);
            qf[kt][mt][3] = *(const unsigned*)(Qg + (r + 8) * 32 + c + 8);
        }

    float mrow[2][2] = {{-3.0e38f, -3.0e38f}, {-3.0e38f, -3.0e38f}};
    float srow[2][2] = {};
    float ctx[2][4][4] = {};

    for (int t0 = 0; t0 < 256; t0 += 32) {
        float lg[2][4][4] = {};
        #pragma unroll
        for (int kt = 0; kt < 2; kt++) {
            unsigned bf[4][2];
            #pragma unroll
            for (int p = 0; p < 2; p++) {
                uint32_t a = Ks_s +
                    ((unsigned)((t0 + p * 16 + b_roff) * KP + kt * 16 + b_coff) << 1);
                ldsm_x4(bf[2 * p][0], bf[2 * p][1],
                        bf[2 * p + 1][0], bf[2 * p + 1][1], a);
            }
            #pragma unroll
            for (int mt = 0; mt < 2; mt++)
                #pragma unroll
                for (int nt = 0; nt < 4; nt++)
                    mma_f16(lg[mt][nt], qf[kt][mt], bf[nt], lg[mt][nt]);
        }
        float cmax[2][2] = {{-3.0e38f, -3.0e38f}, {-3.0e38f, -3.0e38f}};
        #pragma unroll
        for (int nt = 0; nt < 4; nt++) {
            float2 b2 = *(const float2*)&Bb[t0 + nt * 8 + (lc4 << 1)];
            #pragma unroll
            for (int mt = 0; mt < 2; mt++) {
                lg[mt][nt][0] += b2.x; lg[mt][nt][1] += b2.y;
                lg[mt][nt][2] += b2.x; lg[mt][nt][3] += b2.y;
                cmax[mt][0] = fmaxf(cmax[mt][0], fmaxf(lg[mt][nt][0], lg[mt][nt][1]));
                cmax[mt][1] = fmaxf(cmax[mt][1], fmaxf(lg[mt][nt][2], lg[mt][nt][3]));
            }
        }
        float corr[2][2];
        #pragma unroll
        for (int mt = 0; mt < 2; mt++)
            #pragma unroll
            for (int hf = 0; hf < 2; hf++) {
                float v = cmax[mt][hf];
                v = fmaxf(v, __shfl_xor_sync(0xFFFFFFFFu, v, 1));
                v = fmaxf(v, __shfl_xor_sync(0xFFFFFFFFu, v, 2));
                float nm = fmaxf(mrow[mt][hf], v);
                corr[mt][hf] = fast_exp2(mrow[mt][hf] - nm);
                mrow[mt][hf] = nm;
            }
        #pragma unroll
        for (int mt = 0; mt < 2; mt++) {
            float c0 = 0.f, c1 = 0.f;
            #pragma unroll
            for (int nt = 0; nt < 4; nt++) {
                float p0 = fast_exp2(lg[mt][nt][0] - mrow[mt][0]);
                float p1 = fast_exp2(lg[mt][nt][1] - mrow[mt][0]);
                float p2 = fast_exp2(lg[mt][nt][2] - mrow[mt][1]);
                float p3 = fast_exp2(lg[mt][nt][3] - mrow[mt][1]);
                c0 += p0 + p1;
                c1 += p2 + p3;
                lg[mt][nt][0] = p0; lg[mt][nt][1] = p1;
                lg[mt][nt][2] = p2; lg[mt][nt][3] = p3;
            }
            srow[mt][0] = srow[mt][0] * corr[mt][0] + c0;
            srow[mt][1] = srow[mt][1] * corr[mt][1] + c1;
        }
        #pragma unroll
        for (int mt = 0; mt < 2; mt++)
            #pragma unroll
            for (int ct = 0; ct < 4; ct++) {
                ctx[mt][ct][0] *= corr[mt][0];
                ctx[mt][ct][1] *= corr[mt][0];
                ctx[mt][ct][2] *= corr[mt][1];
                ctx[mt][ct][3] *= corr[mt][1];
            }
        #pragma unroll
        for (int ks2 = 0; ks2 < 2; ks2++) {
            unsigned pa[2][4];
            #pragma unroll
            for (int mt = 0; mt < 2; mt++) {
                pa[mt][0] = pack_h2(lg[mt][2 * ks2][0],     lg[mt][2 * ks2][1]);
                pa[mt][1] = pack_h2(lg[mt][2 * ks2][2],     lg[mt][2 * ks2][3]);
                pa[mt][2] = pack_h2(lg[mt][2 * ks2 + 1][0], lg[mt][2 * ks2 + 1][1]);
                pa[mt][3] = pack_h2(lg[mt][2 * ks2 + 1][2], lg[mt][2 * ks2 + 1][3]);
            }
            unsigned vb[4][2];
            #pragma unroll
            for (int p = 0; p < 2; p++) {
                uint32_t a = Vt_s +
                    ((unsigned)((p * 16 + b_roff) * VP + t0 + ks2 * 16 + b_coff) << 1);
                ldsm_x4(vb[2 * p][0], vb[2 * p][1],
                        vb[2 * p + 1][0], vb[2 * p + 1][1], a);
            }
            #pragma unroll
            for (int mt = 0; mt < 2; mt++)
                #pragma unroll
                for (int ct = 0; ct < 4; ct++)
                    mma_f16(ctx[mt][ct], pa[mt], vb[ct], ctx[mt][ct]);
        }
    }

    float inv[2][2];
    #pragma unroll
    for (int mt = 0; mt < 2; mt++)
        #pragma unroll
        for (int hf = 0; hf < 2; hf++) {
            float v = srow[mt][hf];
            v += __shfl_xor_sync(0xFFFFFFFFu, v, 1);
            v += __shfl_xor_sync(0xFFFFFFFFu, v, 2);
            inv[mt][hf] = 1.0f / v;
        }
    #pragma unroll
    for (int mt = 0; mt < 2; mt++)
        #pragma unroll
        for (int ct = 0; ct < 4; ct++) {
            int c = ct * 8 + (lc4 << 1);
            #pragma unroll
            for (int hf = 0; hf < 2; hf++) {
                int s = qb + mt * 16 + lr + hf * 8;
                float2 g2 = __half22float2(*(const __half2*)(Gg + s * 32 + c));
                float ox = ctx[mt][ct][hf * 2 + 0] * inv[mt][hf] * g2.x;
                float oy = ctx[mt][ct][hf * 2 + 1] * inv[mt][hf] * g2.y;
                *(__half2*)(g_CTXh + ((size_t)(l * SDIM + s)) * DDIM + h * CN + c) =
                    __floats2half2_rn(ox, oy);
            }
        }
}

// ============================================================
// Output GEMM (R9-exact)
// ============================================================
__global__ __launch_bounds__(256, 2) void out_mma_kernel(
    const float* __restrict__ bo, float* __restrict__ out) {
    extern __shared__ __half sbuf[];

    int tid = threadIdx.x, warp = tid >> 5, lane = tid & 31;
    int lr = lane >> 2, lc4 = lane & 3;
    int wm = (warp >> 1) << 5;
    int wn = (warp & 1) << 6;

    int r0 = blockIdx.x << 7;
    int n0 = blockIdx.y << 7;
    const __half* W = g_Wh + (size_t)4 * DDIM * DDIM;

    int row0 = tid >> 2,         col0 = (tid & 3) << 3;
    int row1 = (tid + 256) >> 2, col1 = col0;
    const __half* Aip0 = g_CTXh + (size_t)(r0 + row0) * 256 + col0;
    const __half* Aip1 = g_CTXh + (size_t)(r0 + row1) * 256 + col1;
    const __half* Bip0 = W      + (size_t)(n0 + row0) * 256 + col0;
    const __half* Bip1 = W      + (size_t)(n0 + row1) * 256 + col1;

    uint32_t sb = (uint32_t)__cvta_generic_to_shared(sbuf);
    uint32_t dA0 = sb + ((unsigned)(row0 * 40 + col0) << 1);
    uint32_t dA1 = sb + ((unsigned)(row1 * 40 + col1) << 1);
    uint32_t dB0 = dA0 + GSTG * 2;
    uint32_t dB1 = dA1 + GSTG * 2;
    const uint32_t stg = 2 * GSTG * 2;

    int li15 = lane & 15, li7 = lane & 7;
    int a_coff = (lane >> 4) << 3;
    int b_roff = ((lane >> 4) << 3) + li7;
    int b_coff = ((lane >> 3) & 1) << 3;

    float acc[16][4] = {};

    #pragma unroll
    for (int s = 0; s < 2; s++) {
        int k0 = s * 32;
        cp16(dA0 + s * stg, Aip0 + k0);
        cp16(dA1 + s * stg, Aip1 + k0);
        cp16(dB0 + s * stg, Bip0 + k0);
        cp16(dB1 + s * stg, Bip1 + k0);
        cp_commit();
    }

    for (int t = 0; t < 8; t++) {
        if (t < 7) cp_wait<1>(); else cp_wait<0>();
        __syncthreads();
        if (t + 2 < 8) {
            int s = (t + 2) % 3;
            int k0 = (t + 2) * 32;
            cp16(dA0 + s * stg, Aip0 + k0);
            cp16(dA1 + s * stg, Aip1 + k0);
            cp16(dB0 + s * stg, Bip0 + k0);
            cp16(dB1 + s * stg, Bip1 + k0);
            cp_commit();
        }
        uint32_t As_s = sb + (t % 3) * stg;
        uint32_t Bs_s = As_s + GSTG * 2;
        #pragma unroll
        for (int ks = 0; ks < 2; ks++) {
            unsigned af[2][4], bf[8][2];
            #pragma unroll
            for (int mt = 0; mt < 2; mt++) {
                uint32_t a = As_s +
                    ((unsigned)((wm + mt * 16 + li15) * 40 + ks * 16 + a_coff) << 1);
                ldsm_x4(af[mt][0], af[mt][1], af[mt][2], af[mt][3], a);
            }
            #pragma unroll
            for (int p = 0; p < 4; p++) {
                uint32_t b = Bs_s +
                    ((unsigned)((wn + p * 16 + b_roff) * 40 + ks * 16 + b_coff) << 1);
                ldsm_x4(bf[2 * p][0], bf[2 * p][1],
                        bf[2 * p + 1][0], bf[2 * p + 1][1], b);
            }
            #pragma unroll
            for (int mt = 0; mt < 2; mt++)
                #pragma unroll
                for (int nt = 0; nt < 8; nt++)
                    mma_f16(acc[mt * 8 + nt], af[mt], bf[nt], acc[mt * 8 + nt]);
        }
    }

    #pragma unroll
    for (int mt = 0; mt < 2; mt++)
        #pragma unroll
        for (int nt = 0; nt < 8; nt++) {
            int n = n0 + wn + nt * 8 + (lc4 << 1);
            #pragma unroll
            for (int hf = 0; hf < 2; hf++) {
                int r = r0 + wm + mt * 16 + lr + hf * 8;
                int l = r >> 8, s = r & 255;
                float2 o;
                o.x = acc[mt * 8 + nt][hf * 2 + 0] + bo[n];
                o.y = acc[mt * 8 + nt][hf * 2 + 1] + bo[n + 1];
                *(float2*)(out + (size_t)(s * LDIM + l) * DDIM + n) = o;
            }
        }
}

// ============================================================
extern "C" void kernel_launch(void* const* d_in, const int* in_sizes, int n_in,
                              void* d_out, int out_size) {
    const float* m        = (const float*)d_in[0];
    const void*  seqp     = d_in[1];
    const void*  resp     = d_in[2];
    const float* ln_scale = (const float*)d_in[3];
    const float* ln_bias  = (const float*)d_in[4];
    const float* wq       = (const float*)d_in[5];
    const float* wk       = (const float*)d_in[6];
    const float* wv       = (const float*)d_in[7];
    const float* wg       = (const float*)d_in[8];
    const float* bg       = (const float*)d_in[9];
    const float* wo       = (const float*)d_in[10];
    const float* bo       = (const float*)d_in[11];
    float* out = (float*)d_out;

    cudaFuncSetAttribute(proj_mma_kernel,
                         cudaFuncAttributeMaxDynamicSharedMemorySize, GEMM_SMEM_BYTES);
    cudaFuncSetAttribute(out_mma_kernel,
                         cudaFuncAttributeMaxDynamicSharedMemorySize, GEMM_SMEM_BYTES);
    cudaFuncSetAttribute(attn_mma_kernel,
                         cudaFuncAttributeMaxDynamicSharedMemorySize, ATTN_SMEM_BYTES);

    pre_kernel<<<LNB + WCB + MKB, 256>>>(m, ln_scale, ln_bias,
                                         wq, wk, wv, wg, wo, seqp, resp);
    proj_mma_kernel<<<dim3(NROWS / 128, 8), 256, GEMM_SMEM_BYTES>>>(bg);
    attn_mma_kernel<<<LDIM * HN, 256, ATTN_SMEM_BYTES>>>();
    out_mma_kernel<<<dim3(NROWS / 128, 2), 256, GEMM_SMEM_BYTES>>>(bo, out);
}

// round 17
// speedup vs baseline: 1.0249x; 1.0124x over previous
#include <cuda_runtime.h>
#include <cuda_fp16.h>
#include <cstdint>
#include <cstddef>

#define SDIM 256
#define LDIM 192
#define DDIM 256
#define HN   8
#define CN   32
#define NROWS (LDIM*SDIM)
#define SEG  ((size_t)NROWS*DDIM)

#define QSCALE (0.17677669529663687f * 1.4426950408889634f)
#define BIASL2 (-10000.0f * 1.4426950408889634f)

__device__ __half g_XNh[(size_t)NROWS*DDIM];
__device__ __half g_P[(size_t)4*NROWS*DDIM];
__device__ __half g_CTXh[(size_t)NROWS*DDIM];
__device__ __half g_Wh[(size_t)5*DDIM*DDIM];
__device__ float  g_bias[LDIM*SDIM];

// ---------- helpers ----------
__device__ __forceinline__ void mma_f16(float* d, const unsigned* a,
                                        const unsigned* b, const float* c) {
    asm("mma.sync.aligned.m16n8k16.row.col.f32.f16.f16.f32 "
        "{%0,%1,%2,%3}, {%4,%5,%6,%7}, {%8,%9}, {%10,%11,%12,%13};"
        : "=f"(d[0]), "=f"(d[1]), "=f"(d[2]), "=f"(d[3])
        : "r"(a[0]), "r"(a[1]), "r"(a[2]), "r"(a[3]),
          "r"(b[0]), "r"(b[1]),
          "f"(c[0]), "f"(c[1]), "f"(c[2]), "f"(c[3]));
}
__device__ __forceinline__ void ldsm_x4(unsigned& r0, unsigned& r1,
                                        unsigned& r2, unsigned& r3,
                                        uint32_t addr) {
    asm volatile("ldmatrix.sync.aligned.m8n8.x4.shared.b16 {%0,%1,%2,%3}, [%4];"
        : "=r"(r0), "=r"(r1), "=r"(r2), "=r"(r3) : "r"(addr));
}
__device__ __forceinline__ void cp16(uint32_t dst, const void* src) {
    asm volatile("cp.async.cg.shared.global [%0], [%1], 16;"
        :: "r"(dst), "l"(src));
}
__device__ __forceinline__ void cp_commit() {
    asm volatile("cp.async.commit_group;");
}
template <int N>
__device__ __forceinline__ void cp_wait() {
    asm volatile("cp.async.wait_group %0;" :: "n"(N));
}
__device__ __forceinline__ unsigned pack_h2(float a, float b) {
    __half2 h = __floats2half2_rn(a, b);
    return *(unsigned*)&h;
}
__device__ __forceinline__ float fast_exp2(float x) {
    float y;
    asm("ex2.approx.f32 %0, %1;" : "=f"(y) : "f"(x));
    return y;
}

// ============================================================
// Fused preprocessing: ln / wconv / mask in one launch.
// ============================================================
#define LNB (NROWS / 4)
#define WCB (5 * DDIM * DDIM / 256)
#define MKB LDIM

__device__ __forceinline__ int classify_words(const int* w, int nwords) {
    int wordlike = 1;
    for (int i = 0; i < nwords; i++) {
        int v = w[i];
        if (v != 0 && v != 1 && v != 0x3F800000) wordlike = 0;
    }
    return wordlike;
}

__global__ __launch_bounds__(256) void pre_kernel(
    const float* __restrict__ m,
    const float* __restrict__ scale,
    const float* __restrict__ bias,
    const float* __restrict__ wq, const float* __restrict__ wk,
    const float* __restrict__ wv, const float* __restrict__ wg,
    const float* __restrict__ wo,
    const void* __restrict__ seqp, const void* __restrict__ resp) {
    int bid = blockIdx.x;
    if (bid < LNB) {
        int r = bid * 4 + (threadIdx.x >> 6);
        int l = r >> 8;
        int s = r & 255;
        int c0 = (threadIdx.x & 63) << 2;

        float4 v = *(const float4*)(m + ((size_t)(s * LDIM + l)) * DDIM + c0);
        float sum = (v.x + v.y) + (v.z + v.w);
        float sq  = (v.x * v.x + v.y * v.y) + (v.z * v.z + v.w * v.w);
        #pragma unroll
        for (int o = 16; o > 0; o >>= 1) {
            sum += __shfl_xor_sync(0xFFFFFFFFu, sum, o);
            sq  += __shfl_xor_sync(0xFFFFFFFFu, sq, o);
        }
        __shared__ float ssum[8], ssq[8];
        int w = threadIdx.x >> 5;
        if ((threadIdx.x & 31) == 0) { ssum[w] = sum; ssq[w] = sq; }
        __syncthreads();
        int wp = (threadIdx.x >> 6) << 1;
        float S = ssum[wp] + ssum[wp + 1];
        float Q = ssq[wp]  + ssq[wp + 1];
        float mu   = S * (1.0f / DDIM);
        float var  = Q * (1.0f / DDIM) - mu * mu;
        float rstd = rsqrtf(var + 1e-5f);

        float4 sc = *(const float4*)(scale + c0);
        float4 bi = *(const float4*)(bias + c0);
        __half2 h0 = __floats2half2_rn((v.x - mu) * rstd * sc.x + bi.x,
                                       (v.y - mu) * rstd * sc.y + bi.y);
        __half2 h1 = __floats2half2_rn((v.z - mu) * rstd * sc.z + bi.z,
                                       (v.w - mu) * rstd * sc.w + bi.w);
        uint2 o;
        o.x = *(unsigned*)&h0;
        o.y = *(unsigned*)&h1;
        *(uint2*)(g_XNh + (size_t)r * DDIM + c0) = o;
    } else if (bid < LNB + WCB) {
        int j = (bid - LNB) * 256 + threadIdx.x;
        int mat = j >> 16;
        int i = j & 65535;
        const float* src = (mat == 0) ? wq : (mat == 1) ? wk :
                           (mat == 2) ? wv : (mat == 3) ? wg : wo;
        g_Wh[(size_t)mat * DDIM * DDIM + i] = __float2half(src[i]);
    } else {
        __shared__ int s_seqw, s_resw;
        if (threadIdx.x == 0) {
            s_seqw = classify_words((const int*)seqp, 64);
            s_resw = classify_words((const int*)resp, 48);
        }
        __syncthreads();
        const int seqw = s_seqw, resw = s_resw;
        int idx = (bid - LNB - WCB) * 256 + threadIdx.x;
        int l = idx >> 8;
        int t = idx & 255;
        int rp = resw ? (((const int*)resp)[l] != 0)
                      : (((const unsigned char*)resp)[l] != 0);
        int sp = seqw ? (((const int*)seqp)[t] != 0)
                      : (((const unsigned char*)seqp)[t] != 0);
        g_bias[idx] = (rp | sp) ? BIASL2 : 0.0f;
    }
}

// ============================================================
// Projection GEMM: BM=128 BN=128 BK=64 (4 tiles, half the
// barriers, 96 HMMA/burst). cp.async 3-stage, pitch 72.
// smem/stage 2*128*72*2 = 36864 B; x3 = 110592 B -> 2 CTA/SM.
// ============================================================
#define GP 72                      // smem pitch (halfs)
#define GSTG (128 * GP)            // halfs per matrix per stage
#define STG_BYTES (2 * GSTG * 2)   // both matrices, bytes
#define GEMM_SMEM_BYTES (3 * STG_BYTES)

__global__ __launch_bounds__(256, 2) void proj_mma_kernel(
    const float* __restrict__ bgv) {
    extern __shared__ __half sbuf[];

    int tid = threadIdx.x, warp = tid >> 5, lane = tid & 31;
    int lr = lane >> 2, lc4 = lane & 3;
    int wm = (warp >> 1) << 5;
    int wn = (warp & 1) << 6;

    int r0  = blockIdx.x << 7;
    int mat = blockIdx.y >> 1;
    int n0  = (blockIdx.y & 1) << 7;
    const __half* W = g_Wh + (size_t)mat * DDIM * DDIM;

    // staging: 1024 chunks of 8 halfs per matrix per tile; 4 per thread.
    int srow = tid >> 3, scol = (tid & 7) << 3;
    const __half* Aip = g_XNh + (size_t)(r0 + srow) * 256 + scol;
    const __half* Bip = W     + (size_t)(n0 + srow) * 256 + scol;

    uint32_t sb = (uint32_t)__cvta_generic_to_shared(sbuf);
    uint32_t dA = sb + ((unsigned)(srow * GP + scol) << 1);
    uint32_t dB = dA + GSTG * 2;

    int li15 = lane & 15, li7 = lane & 7;
    int a_coff = (lane >> 4) << 3;
    int b_roff = ((lane >> 4) << 3) + li7;
    int b_coff = ((lane >> 3) & 1) << 3;

    float acc[16][4] = {};

    #pragma unroll
    for (int s = 0; s < 2; s++) {
        int k0 = s * 64;
        uint32_t so = (unsigned)s * STG_BYTES;
        #pragma unroll
        for (int i = 0; i < 4; i++) {
            cp16(dA + so + (unsigned)i * 32 * GP * 2, Aip + (size_t)i * 32 * 256 + k0);
            cp16(dB + so + (unsigned)i * 32 * GP * 2, Bip + (size_t)i * 32 * 256 + k0);
        }
        cp_commit();
    }

    for (int t = 0; t < 4; t++) {
        if (t < 3) cp_wait<1>(); else cp_wait<0>();
        __syncthreads();
        if (t + 2 < 4) {
            int s = (t + 2) % 3;
            int k0 = (t + 2) * 64;
            uint32_t so = (unsigned)s * STG_BYTES;
            #pragma unroll
            for (int i = 0; i < 4; i++) {
                cp16(dA + so + (unsigned)i * 32 * GP * 2, Aip + (size_t)i * 32 * 256 + k0);
                cp16(dB + so + (unsigned)i * 32 * GP * 2, Bip + (size_t)i * 32 * 256 + k0);
            }
            cp_commit();
        }
        uint32_t As_s = sb + (unsigned)(t % 3) * STG_BYTES;
        uint32_t Bs_s = As_s + GSTG * 2;
        #pragma unroll
        for (int ks = 0; ks < 4; ks++) {
            unsigned af[2][4], bf[8][2];
            #pragma unroll
            for (int mt = 0; mt < 2; mt++) {
                uint32_t a = As_s +
                    ((unsigned)((wm + mt * 16 + li15) * GP + ks * 16 + a_coff) << 1);
                ldsm_x4(af[mt][0], af[mt][1], af[mt][2], af[mt][3], a);
            }
            #pragma unroll
            for (int p = 0; p < 4; p++) {
                uint32_t b = Bs_s +
                    ((unsigned)((wn + p * 16 + b_roff) * GP + ks * 16 + b_coff) << 1);
                ldsm_x4(bf[2 * p][0], bf[2 * p][1],
                        bf[2 * p + 1][0], bf[2 * p + 1][1], b);
            }
            #pragma unroll
            for (int mt = 0; mt < 2; mt++)
                #pragma unroll
                for (int nt = 0; nt < 8; nt++)
                    mma_f16(acc[mt * 8 + nt], af[mt], bf[nt], acc[mt * 8 + nt]);
        }
    }

    #pragma unroll
    for (int mt = 0; mt < 2; mt++)
        #pragma unroll
        for (int nt = 0; nt < 8; nt++) {
            int n = n0 + wn + nt * 8 + (lc4 << 1);
            int h = n >> 5, c = n & 31;
            #pragma unroll
            for (int hf = 0; hf < 2; hf++) {
                int r = r0 + wm + mt * 16 + lr + hf * 8;
                int l = r >> 8, s = r & 255;
                float v0 = acc[mt * 8 + nt][hf * 2 + 0];
                float v1 = acc[mt * 8 + nt][hf * 2 + 1];
                if (mat == 0) {
                    v0 *= QSCALE;
                    v1 *= QSCALE;
                } else if (mat == 3) {
                    v0 = 1.0f / (1.0f + __expf(-(v0 + bgv[n])));
                    v1 = 1.0f / (1.0f + __expf(-(v1 + bgv[n + 1])));
                }
                __half* dst = g_P + (size_t)mat * SEG
                            + ((size_t)((l * HN + h) * SDIM + s)) * CN + c;
                *(__half2*)dst = __floats2half2_rn(v0, v1);
            }
        }
}

// ============================================================
// Attention (R14-exact): 1 CTA per (l,h), m=32 warps, 2 CTA/SM,
// uint4 staging, exp2 softmax, deferred sums.
// ============================================================
#define KP 40
#define VP 264
#define ATTN_SMEM_BYTES (256*KP*2 + 32*VP*2 + 256*4)

__global__ __launch_bounds__(256, 2) void attn_mma_kernel() {
    extern __shared__ char smem_raw[];
    __half* Ks = (__half*)smem_raw;
    __half* Vt = (__half*)(smem_raw + 256 * KP * 2);
    float*  Bb = (float*)(smem_raw + 256 * KP * 2 + 32 * VP * 2);

    int lh = blockIdx.x;
    int l = lh >> 3, h = lh & 7;
    size_t base = (size_t)lh * SDIM * CN;
    const __half* Qg = g_P + base;
    const __half* Kg = g_P + SEG + base;
    const __half* Vg = g_P + 2 * SEG + base;
    const __half* Gg = g_P + 3 * SEG + base;

    int tid = threadIdx.x, warp = tid >> 5, lane = tid & 31;
    int lr = lane >> 2, lc4 = lane & 3;
    int li7 = lane & 7;
    int b_roff = ((lane >> 4) << 3) + li7;
    int b_coff = ((lane >> 3) & 1) << 3;

    uint32_t Ks_s = (uint32_t)__cvta_generic_to_shared(Ks);
    uint32_t Vt_s = (uint32_t)__cvta_generic_to_shared(Vt);

    #pragma unroll
    for (int i = 0; i < 4; i++) {
        int idx = tid + (i << 8);
        int t = idx >> 2, c8 = (idx & 3) << 3;
        uint4 kv = *(const uint4*)(Kg + t * 32 + c8);
        *(uint4*)(Ks + t * KP + c8) = kv;
        uint4 vv = *(const uint4*)(Vg + t * 32 + c8);
        const __half2* vh = (const __half2*)&vv;
        #pragma unroll
        for (int j = 0; j < 4; j++) {
            Vt[(c8 + 2 * j + 0) * VP + t] = __low2half(vh[j]);
            Vt[(c8 + 2 * j + 1) * VP + t] = __high2half(vh[j]);
        }
    }
    Bb[tid] = g_bias[l * SDIM + tid];
    __syncthreads();

    int qb = warp << 5;
    unsigned qf[2][2][4];
    #pragma unroll
    for (int kt = 0; kt < 2; kt++)
        #pragma unroll
        for (int mt = 0; mt < 2; mt++) {
            int r = qb + mt * 16 + lr;
            int c = kt * 16 + (lc4 << 1);
            qf[kt][mt][0] = *(const unsigned*)(Qg + r * 32 + c);
            qf[kt][mt][1] = *(const unsigned*)(Qg + (r + 8) * 32 + c);
            qf[kt][mt][2] = *(const unsigned*)(Qg + r * 32 + c + 8);
            qf[kt][mt][3] = *(const unsigned*)(Qg + (r + 8) * 32 + c + 8);
        }

    float mrow[2][2] = {{-3.0e38f, -3.0e38f}, {-3.0e38f, -3.0e38f}};
    float srow[2][2] = {};
    float ctx[2][4][4] = {};

    for (int t0 = 0; t0 < 256; t0 += 32) {
        float lg[2][4][4] = {};
        #pragma unroll
        for (int kt = 0; kt < 2; kt++) {
            unsigned bf[4][2];
            #pragma unroll
            for (int p = 0; p < 2; p++) {
                uint32_t a = Ks_s +
                    ((unsigned)((t0 + p * 16 + b_roff) * KP + kt * 16 + b_coff) << 1);
                ldsm_x4(bf[2 * p][0], bf[2 * p][1],
                        bf[2 * p + 1][0], bf[2 * p + 1][1], a);
            }
            #pragma unroll
            for (int mt = 0; mt < 2; mt++)
                #pragma unroll
                for (int nt = 0; nt < 4; nt++)
                    mma_f16(lg[mt][nt], qf[kt][mt], bf[nt], lg[mt][nt]);
        }
        float cmax[2][2] = {{-3.0e38f, -3.0e38f}, {-3.0e38f, -3.0e38f}};
        #pragma unroll
        for (int nt = 0; nt < 4; nt++) {
            float2 b2 = *(const float2*)&Bb[t0 + nt * 8 + (lc4 << 1)];
            #pragma unroll
            for (int mt = 0; mt < 2; mt++) {
                lg[mt][nt][0] += b2.x; lg[mt][nt][1] += b2.y;
                lg[mt][nt][2] += b2.x; lg[mt][nt][3] += b2.y;
                cmax[mt][0] = fmaxf(cmax[mt][0], fmaxf(lg[mt][nt][0], lg[mt][nt][1]));
                cmax[mt][1] = fmaxf(cmax[mt][1], fmaxf(lg[mt][nt][2], lg[mt][nt][3]));
            }
        }
        float corr[2][2];
        #pragma unroll
        for (int mt = 0; mt < 2; mt++)
            #pragma unroll
            for (int hf = 0; hf < 2; hf++) {
                float v = cmax[mt][hf];
                v = fmaxf(v, __shfl_xor_sync(0xFFFFFFFFu, v, 1));
                v = fmaxf(v, __shfl_xor_sync(0xFFFFFFFFu, v, 2));
                float nm = fmaxf(mrow[mt][hf], v);
                corr[mt][hf] = fast_exp2(mrow[mt][hf] - nm);
                mrow[mt][hf] = nm;
            }
        #pragma unroll
        for (int mt = 0; mt < 2; mt++) {
            float c0 = 0.f, c1 = 0.f;
            #pragma unroll
            for (int nt = 0; nt < 4; nt++) {
                float p0 = fast_exp2(lg[mt][nt][0] - mrow[mt][0]);
                float p1 = fast_exp2(lg[mt][nt][1] - mrow[mt][0]);
                float p2 = fast_exp2(lg[mt][nt][2] - mrow[mt][1]);
                float p3 = fast_exp2(lg[mt][nt][3] - mrow[mt][1]);
                c0 += p0 + p1;
                c1 += p2 + p3;
                lg[mt][nt][0] = p0; lg[mt][nt][1] = p1;
                lg[mt][nt][2] = p2; lg[mt][nt][3] = p3;
            }
            srow[mt][0] = srow[mt][0] * corr[mt][0] + c0;
            srow[mt][1] = srow[mt][1] * corr[mt][1] + c1;
        }
        #pragma unroll
        for (int mt = 0; mt < 2; mt++)
            #pragma unroll
            for (int ct = 0; ct < 4; ct++) {
                ctx[mt][ct][0] *= corr[mt][0];
                ctx[mt][ct][1] *= corr[mt][0];
                ctx[mt][ct][2] *= corr[mt][1];
                ctx[mt][ct][3] *= corr[mt][1];
            }
        #pragma unroll
        for (int ks2 = 0; ks2 < 2; ks2++) {
            unsigned pa[2][4];
            #pragma unroll
            for (int mt = 0; mt < 2; mt++) {
                pa[mt][0] = pack_h2(lg[mt][2 * ks2][0],     lg[mt][2 * ks2][1]);
                pa[mt][1] = pack_h2(lg[mt][2 * ks2][2],     lg[mt][2 * ks2][3]);
                pa[mt][2] = pack_h2(lg[mt][2 * ks2 + 1][0], lg[mt][2 * ks2 + 1][1]);
                pa[mt][3] = pack_h2(lg[mt][2 * ks2 + 1][2], lg[mt][2 * ks2 + 1][3]);
            }
            unsigned vb[4][2];
            #pragma unroll
            for (int p = 0; p < 2; p++) {
                uint32_t a = Vt_s +
                    ((unsigned)((p * 16 + b_roff) * VP + t0 + ks2 * 16 + b_coff) << 1);
                ldsm_x4(vb[2 * p][0], vb[2 * p][1],
                        vb[2 * p + 1][0], vb[2 * p + 1][1], a);
            }
            #pragma unroll
            for (int mt = 0; mt < 2; mt++)
                #pragma unroll
                for (int ct = 0; ct < 4; ct++)
                    mma_f16(ctx[mt][ct], pa[mt], vb[ct], ctx[mt][ct]);
        }
    }

    float inv[2][2];
    #pragma unroll
    for (int mt = 0; mt < 2; mt++)
        #pragma unroll
        for (int hf = 0; hf < 2; hf++) {
            float v = srow[mt][hf];
            v += __shfl_xor_sync(0xFFFFFFFFu, v, 1);
            v += __shfl_xor_sync(0xFFFFFFFFu, v, 2);
            inv[mt][hf] = 1.0f / v;
        }
    #pragma unroll
    for (int mt = 0; mt < 2; mt++)
        #pragma unroll
        for (int ct = 0; ct < 4; ct++) {
            int c = ct * 8 + (lc4 << 1);
            #pragma unroll
            for (int hf = 0; hf < 2; hf++) {
                int s = qb + mt * 16 + lr + hf * 8;
                float2 g2 = __half22float2(*(const __half2*)(Gg + s * 32 + c));
                float ox = ctx[mt][ct][hf * 2 + 0] * inv[mt][hf] * g2.x;
                float oy = ctx[mt][ct][hf * 2 + 1] * inv[mt][hf] * g2.y;
                *(__half2*)(g_CTXh + ((size_t)(l * SDIM + s)) * DDIM + h * CN + c) =
                    __floats2half2_rn(ox, oy);
            }
        }
}

// ============================================================
// Output GEMM: BK=64, pitch 72, 4 tiles.
// ============================================================
__global__ __launch_bounds__(256, 2) void out_mma_kernel(
    const float* __restrict__ bo, float* __restrict__ out) {
    extern __shared__ __half sbuf[];

    int tid = threadIdx.x, warp = tid >> 5, lane = tid & 31;
    int lr = lane >> 2, lc4 = lane & 3;
    int wm = (warp >> 1) << 5;
    int wn = (warp & 1) << 6;

    int r0 = blockIdx.x << 7;
    int n0 = blockIdx.y << 7;
    const __half* W = g_Wh + (size_t)4 * DDIM * DDIM;

    int srow = tid >> 3, scol = (tid & 7) << 3;
    const __half* Aip = g_CTXh + (size_t)(r0 + srow) * 256 + scol;
    const __half* Bip = W      + (size_t)(n0 + srow) * 256 + scol;

    uint32_t sb = (uint32_t)__cvta_generic_to_shared(sbuf);
    uint32_t dA = sb + ((unsigned)(srow * GP + scol) << 1);
    uint32_t dB = dA + GSTG * 2;

    int li15 = lane & 15, li7 = lane & 7;
    int a_coff = (lane >> 4) << 3;
    int b_roff = ((lane >> 4) << 3) + li7;
    int b_coff = ((lane >> 3) & 1) << 3;

    float acc[16][4] = {};

    #pragma unroll
    for (int s = 0; s < 2; s++) {
        int k0 = s * 64;
        uint32_t so = (unsigned)s * STG_BYTES;
        #pragma unroll
        for (int i = 0; i < 4; i++) {
            cp16(dA + so + (unsigned)i * 32 * GP * 2, Aip + (size_t)i * 32 * 256 + k0);
            cp16(dB + so + (unsigned)i * 32 * GP * 2, Bip + (size_t)i * 32 * 256 + k0);
        }
        cp_commit();
    }

    for (int t = 0; t < 4; t++) {
        if (t < 3) cp_wait<1>(); else cp_wait<0>();
        __syncthreads();
        if (t + 2 < 4) {
            int s = (t + 2) % 3;
            int k0 = (t + 2) * 64;
            uint32_t so = (unsigned)s * STG_BYTES;
            #pragma unroll
            for (int i = 0; i < 4; i++) {
                cp16(dA + so + (unsigned)i * 32 * GP * 2, Aip + (size_t)i * 32 * 256 + k0);
                cp16(dB + so + (unsigned)i * 32 * GP * 2, Bip + (size_t)i * 32 * 256 + k0);
            }
            cp_commit();
        }
        uint32_t As_s = sb + (unsigned)(t % 3) * STG_BYTES;
        uint32_t Bs_s = As_s + GSTG * 2;
        #pragma unroll
        for (int ks = 0; ks < 4; ks++) {
            unsigned af[2][4], bf[8][2];
            #pragma unroll
            for (int mt = 0; mt < 2; mt++) {
                uint32_t a = As_s +
                    ((unsigned)((wm + mt * 16 + li15) * GP + ks * 16 + a_coff) << 1);
                ldsm_x4(af[mt][0], af[mt][1], af[mt][2], af[mt][3], a);
            }
            #pragma unroll
            for (int p = 0; p < 4; p++) {
                uint32_t b = Bs_s +
                    ((unsigned)((wn + p * 16 + b_roff) * GP + ks * 16 + b_coff) << 1);
                ldsm_x4(bf[2 * p][0], bf[2 * p][1],
                        bf[2 * p + 1][0], bf[2 * p + 1][1], b);
            }
            #pragma unroll
            for (int mt = 0; mt < 2; mt++)
                #pragma unroll
                for (int nt = 0; nt < 8; nt++)
                    mma_f16(acc[mt * 8 + nt], af[mt], bf[nt], acc[mt * 8 + nt]);
        }
    }

    #pragma unroll
    for (int mt = 0; mt < 2; mt++)
        #pragma unroll
        for (int nt = 0; nt < 8; nt++) {
            int n = n0 + wn + nt * 8 + (lc4 << 1);
            #pragma unroll
            for (int hf = 0; hf < 2; hf++) {
                int r = r0 + wm + mt * 16 + lr + hf * 8;
                int l = r >> 8, s = r & 255;
                float2 o;
                o.x = acc[mt * 8 + nt][hf * 2 + 0] + bo[n];
                o.y = acc[mt * 8 + nt][hf * 2 + 1] + bo[n + 1];
                *(float2*)(out + (size_t)(s * LDIM + l) * DDIM + n) = o;
            }
        }
}

// ============================================================
extern "C" void kernel_launch(void* const* d_in, const int* in_sizes, int n_in,
                              void* d_out, int out_size) {
    const float* m        = (const float*)d_in[0];
    const void*  seqp     = d_in[1];
    const void*  resp     = d_in[2];
    const float* ln_scale = (const float*)d_in[3];
    const float* ln_bias  = (const float*)d_in[4];
    const float* wq       = (const float*)d_in[5];
    const float* wk       = (const float*)d_in[6];
    const float* wv       = (const float*)d_in[7];
    const float* wg       = (const float*)d_in[8];
    const float* bg       = (const float*)d_in[9];
    const float* wo       = (const float*)d_in[10];
    const float* bo       = (const float*)d_in[11];
    float* out = (float*)d_out;

    cudaFuncSetAttribute(proj_mma_kernel,
                         cudaFuncAttributeMaxDynamicSharedMemorySize, GEMM_SMEM_BYTES);
    cudaFuncSetAttribute(out_mma_kernel,
                         cudaFuncAttributeMaxDynamicSharedMemorySize, GEMM_SMEM_BYTES);
    cudaFuncSetAttribute(attn_mma_kernel,
                         cudaFuncAttributeMaxDynamicSharedMemorySize, ATTN_SMEM_BYTES);

    pre_kernel<<<LNB + WCB + MKB, 256>>>(m, ln_scale, ln_bias,
                                         wq, wk, wv, wg, wo, seqp, resp);
    proj_mma_kernel<<<dim3(NROWS / 128, 8), 256, GEMM_SMEM_BYTES>>>(bg);
    attn_mma_kernel<<<LDIM * HN, 256, ATTN_SMEM_BYTES>>>();
    out_mma_kernel<<<dim3(NROWS / 128, 2), 256, GEMM_SMEM_BYTES>>>(bo, out);
}